// round 4
// baseline (speedup 1.0000x reference)
#include <cuda_runtime.h>
#include <cstdint>

#define N_NODES_MAX 50000
#define FDIM 64
#define HDIM 128

// Scratch (no allocations allowed in kernel_launch)
__device__ __align__(16) float g_h[(size_t)N_NODES_MAX * FDIM];     // (1+eps)*x + agg
__device__ __align__(16) float g_hid[(size_t)N_NODES_MAX * HDIM];   // relu(h@W1+b1)

// ---------------------------------------------------------------------------
// Kernel 1: h = (1+eps) * x
// ---------------------------------------------------------------------------
__global__ void init_h_kernel(const float* __restrict__ x,
                              const float* __restrict__ eps, int n4) {
    int i = blockIdx.x * blockDim.x + threadIdx.x;
    if (i < n4) {
        float s = 1.0f + eps[0];
        float4 v = ((const float4*)x)[i];
        v.x *= s; v.y *= s; v.z *= s; v.w *= s;
        ((float4*)g_h)[i] = v;
    }
}

// ---------------------------------------------------------------------------
// Kernel 2: scatter-add. Thread = (edge, 16-float4-chunk).
// edge_index is int32 (jax x64-disabled downcasts the "int64" request).
// gather x[col] (L2-resident) and red.global.add.v4.f32 into h[row].
// ---------------------------------------------------------------------------
__global__ void scatter_kernel(const float* __restrict__ x,
                               const int* __restrict__ ei, int E) {
    long long i = (long long)blockIdx.x * blockDim.x + threadIdx.x;
    if (i >= (long long)E * 16) return;
    int e = (int)(i >> 4);
    int c = (int)(i & 15);
    int row = ei[e];
    int col = ei[E + e];
    float4 v = *(const float4*)(x + (size_t)col * FDIM + c * 4);
    float* dst = g_h + (size_t)row * FDIM + c * 4;
    asm volatile("red.global.add.v4.f32 [%0], {%1,%2,%3,%4};"
                 :: "l"(dst), "f"(v.x), "f"(v.y), "f"(v.z), "f"(v.w)
                 : "memory");
}

// ---------------------------------------------------------------------------
// Kernel 3: hidden = relu(h @ W1 + b1).  32 nodes/block, 128 threads.
// tx (16) covers 8 of 128 output cols, ty (8) covers 4 of 32 nodes.
// ---------------------------------------------------------------------------
#define L1_NODES 32
__global__ __launch_bounds__(128) void mlp1_kernel(const float* __restrict__ W1,
                                                   const float* __restrict__ b1,
                                                   int N) {
    __shared__ float W1s[FDIM * HDIM];        // 32 KB
    __shared__ float hs[L1_NODES][FDIM + 4];  // pad 68 -> conflict-free
    __shared__ float b1s[HDIM];

    int tid = threadIdx.x;
    for (int i = tid; i < FDIM * HDIM / 4; i += 128)
        ((float4*)W1s)[i] = ((const float4*)W1)[i];
    if (tid < HDIM) b1s[tid] = b1[tid];

    int nb = blockIdx.x * L1_NODES;
    for (int i = tid; i < L1_NODES * (FDIM / 4); i += 128) {
        int n  = i / (FDIM / 4);
        int cc = i % (FDIM / 4);
        int node = nb + n;
        float4 v = make_float4(0.f, 0.f, 0.f, 0.f);
        if (node < N) v = ((const float4*)(g_h + (size_t)node * FDIM))[cc];
        *((float4*)&hs[n][cc * 4]) = v;
    }
    __syncthreads();

    int tx = tid & 15;
    int ty = tid >> 4;
    float acc[4][8];
#pragma unroll
    for (int q = 0; q < 4; q++)
#pragma unroll
        for (int j = 0; j < 8; j++)
            acc[q][j] = b1s[tx * 8 + j];

#pragma unroll 4
    for (int k = 0; k < FDIM; k++) {
        float4 w0 = *((const float4*)&W1s[k * HDIM + tx * 8]);
        float4 w1 = *((const float4*)&W1s[k * HDIM + tx * 8 + 4]);
#pragma unroll
        for (int q = 0; q < 4; q++) {
            float a = hs[ty * 4 + q][k];
            acc[q][0] += a * w0.x; acc[q][1] += a * w0.y;
            acc[q][2] += a * w0.z; acc[q][3] += a * w0.w;
            acc[q][4] += a * w1.x; acc[q][5] += a * w1.y;
            acc[q][6] += a * w1.z; acc[q][7] += a * w1.w;
        }
    }

#pragma unroll
    for (int q = 0; q < 4; q++) {
        int node = nb + ty * 4 + q;
        if (node < N) {
            float4 o0, o1;
            o0.x = fmaxf(acc[q][0], 0.f); o0.y = fmaxf(acc[q][1], 0.f);
            o0.z = fmaxf(acc[q][2], 0.f); o0.w = fmaxf(acc[q][3], 0.f);
            o1.x = fmaxf(acc[q][4], 0.f); o1.y = fmaxf(acc[q][5], 0.f);
            o1.z = fmaxf(acc[q][6], 0.f); o1.w = fmaxf(acc[q][7], 0.f);
            float* dst = g_hid + (size_t)node * HDIM + tx * 8;
            *((float4*)dst)       = o0;
            *((float4*)(dst + 4)) = o1;
        }
    }
}

// ---------------------------------------------------------------------------
// Kernel 4: out = hidden @ W2 + b2.  16 nodes/block, 128 threads.
// tx (16) covers 4 of 64 output cols, ty (8) covers 2 of 16 nodes.
// ---------------------------------------------------------------------------
#define L2_NODES 16
__global__ __launch_bounds__(128) void mlp2_kernel(const float* __restrict__ W2,
                                                   const float* __restrict__ b2,
                                                   float* __restrict__ out,
                                                   int N) {
    __shared__ float W2s[HDIM * FDIM];          // 32 KB
    __shared__ float hids[L2_NODES][HDIM + 4];  // pad 132 -> conflict-free
    __shared__ float b2s[FDIM];

    int tid = threadIdx.x;
    for (int i = tid; i < HDIM * FDIM / 4; i += 128)
        ((float4*)W2s)[i] = ((const float4*)W2)[i];
    if (tid < FDIM) b2s[tid] = b2[tid];

    int nb = blockIdx.x * L2_NODES;
    for (int i = tid; i < L2_NODES * (HDIM / 4); i += 128) {
        int n  = i / (HDIM / 4);
        int cc = i % (HDIM / 4);
        int node = nb + n;
        float4 v = make_float4(0.f, 0.f, 0.f, 0.f);
        if (node < N) v = ((const float4*)(g_hid + (size_t)node * HDIM))[cc];
        *((float4*)&hids[n][cc * 4]) = v;
    }
    __syncthreads();

    int tx = tid & 15;
    int ty = tid >> 4;
    float acc[2][4];
#pragma unroll
    for (int q = 0; q < 2; q++)
#pragma unroll
        for (int j = 0; j < 4; j++)
            acc[q][j] = b2s[tx * 4 + j];

#pragma unroll 4
    for (int k = 0; k < HDIM; k++) {
        float4 w = *((const float4*)&W2s[k * FDIM + tx * 4]);
        float a0 = hids[ty * 2][k];
        float a1 = hids[ty * 2 + 1][k];
        acc[0][0] += a0 * w.x; acc[0][1] += a0 * w.y;
        acc[0][2] += a0 * w.z; acc[0][3] += a0 * w.w;
        acc[1][0] += a1 * w.x; acc[1][1] += a1 * w.y;
        acc[1][2] += a1 * w.z; acc[1][3] += a1 * w.w;
    }

#pragma unroll
    for (int q = 0; q < 2; q++) {
        int node = nb + ty * 2 + q;
        if (node < N) {
            float4 o;
            o.x = acc[q][0]; o.y = acc[q][1]; o.z = acc[q][2]; o.w = acc[q][3];
            *((float4*)(out + (size_t)node * FDIM + tx * 4)) = o;
        }
    }
}

// ---------------------------------------------------------------------------
extern "C" void kernel_launch(void* const* d_in, const int* in_sizes, int n_in,
                              void* d_out, int out_size) {
    const float* x   = (const float*)d_in[0];
    const int*   ei  = (const int*)d_in[1];      // int32! (jax x64 disabled)
    const float* W1  = (const float*)d_in[2];
    const float* b1  = (const float*)d_in[3];
    const float* W2  = (const float*)d_in[4];
    const float* b2  = (const float*)d_in[5];
    const float* eps = (const float*)d_in[6];
    float* out = (float*)d_out;

    int N = in_sizes[0] / FDIM;       // 50000
    int E = in_sizes[1] / 2;          // 800000

    int n4 = N * FDIM / 4;
    init_h_kernel<<<(n4 + 255) / 256, 256>>>(x, eps, n4);

    long long sthreads = (long long)E * 16;
    int sblocks = (int)((sthreads + 255) / 256);
    scatter_kernel<<<sblocks, 256>>>(x, ei, E);

    mlp1_kernel<<<(N + L1_NODES - 1) / L1_NODES, 128>>>(W1, b1, N);
    mlp2_kernel<<<(N + L2_NODES - 1) / L2_NODES, 128>>>(W2, b2, out, N);
}

// round 5
// speedup vs baseline: 1.5264x; 1.5264x over previous
#include <cuda_runtime.h>
#include <cstdint>

#define N_NODES_MAX 50000
#define FDIM 64
#define HDIM 128

// Scratch (no allocations allowed in kernel_launch)
__device__ __align__(16) float g_h[(size_t)N_NODES_MAX * FDIM];   // (1+eps)*x + agg

// ---------------------------------------------------------------------------
// Kernel 1: h = (1+eps) * x
// ---------------------------------------------------------------------------
__global__ void init_h_kernel(const float* __restrict__ x,
                              const float* __restrict__ eps, int n4) {
    int i = blockIdx.x * blockDim.x + threadIdx.x;
    if (i < n4) {
        float s = 1.0f + eps[0];
        float4 v = ((const float4*)x)[i];
        v.x *= s; v.y *= s; v.z *= s; v.w *= s;
        ((float4*)g_h)[i] = v;
    }
}

// ---------------------------------------------------------------------------
// Kernel 2: scatter-add (near L2 roofline already).
// edge_index is int32. red.global.add.v4.f32 into h[row].
// ---------------------------------------------------------------------------
__global__ void scatter_kernel(const float* __restrict__ x,
                               const int* __restrict__ ei, int E) {
    long long i = (long long)blockIdx.x * blockDim.x + threadIdx.x;
    if (i >= (long long)E * 16) return;
    int e = (int)(i >> 4);
    int c = (int)(i & 15);
    int row = ei[e];
    int col = ei[E + e];
    float4 v = *(const float4*)(x + (size_t)col * FDIM + c * 4);
    float* dst = g_h + (size_t)row * FDIM + c * 4;
    asm volatile("red.global.add.v4.f32 [%0], {%1,%2,%3,%4};"
                 :: "l"(dst), "f"(v.x), "f"(v.y), "f"(v.z), "f"(v.w)
                 : "memory");
}

// ---------------------------------------------------------------------------
// Fused MLP: out = relu(h@W1+b1)@W2 + b2 using tf32 tensor cores with
// 3xTF32 error compensation (hi*hi + hi*lo + lo*hi). fp32 accumulate.
//
// 128 nodes/block, 128 threads = 4 warps, each warp owns 32 rows (2 m16 tiles).
// Hidden activations never leave shared memory.
//
// Shared layout (floats), strides chosen for conflict-free fragment LDS:
//   W1s: 64 x 136   (136 % 32 == 8 -> b-frag banks 8k+n, all distinct)
//   W2s: 128 x 72   (72  % 32 == 8)
//   hs : 128 x 68   (68  % 32 == 4 -> a-frag banks 4m+k, all distinct)
//   hid: 128 x 132  (132 % 32 == 4)
// ---------------------------------------------------------------------------
#define SW1 136
#define SW2 72
#define SH  68
#define SHD 132
#define SM_W1 0
#define SM_W2 (SM_W1 + 64 * SW1)        // 8704
#define SM_H  (SM_W2 + 128 * SW2)       // 17920
#define SM_HD (SM_H + 128 * SH)         // 26624
#define SM_TOTAL (SM_HD + 128 * SHD)    // 43520 floats = 174080 B

__device__ __forceinline__ unsigned f2tf32(float x) {
    unsigned u;
    asm("cvt.rna.tf32.f32 %0, %1;" : "=r"(u) : "f"(x));
    return u;
}

__device__ __forceinline__ void mma8(float* d, const unsigned* a, const unsigned* b) {
    asm volatile(
        "mma.sync.aligned.m16n8k8.row.col.f32.tf32.tf32.f32 "
        "{%0,%1,%2,%3}, {%4,%5,%6,%7}, {%8,%9}, {%0,%1,%2,%3};\n"
        : "+f"(d[0]), "+f"(d[1]), "+f"(d[2]), "+f"(d[3])
        : "r"(a[0]), "r"(a[1]), "r"(a[2]), "r"(a[3]), "r"(b[0]), "r"(b[1]));
}

__global__ __launch_bounds__(128, 1)
void fused_mlp_kernel(const float* __restrict__ W1, const float* __restrict__ b1,
                      const float* __restrict__ W2, const float* __restrict__ b2,
                      float* __restrict__ out, int N) {
    extern __shared__ float sm[];
    float* W1s = sm + SM_W1;
    float* W2s = sm + SM_W2;
    float* hs  = sm + SM_H;
    float* hid = sm + SM_HD;

    const int tid  = threadIdx.x;
    const int lane = tid & 31;
    const int wid  = tid >> 5;
    const int g = lane >> 2;      // groupID   0..7
    const int t = lane & 3;       // tid-in-group 0..3
    const int nb = blockIdx.x * 128;
    const int wm = wid * 32;      // warp row base within tile

    // ---- load W1 (64x128), W2 (128x64), h tile (128x64) into smem ----
#pragma unroll 4
    for (int i = tid; i < 64 * 32; i += 128) {       // W1: 32 float4 per row
        int r = i >> 5, c4 = i & 31;
        ((float4*)(W1s + r * SW1))[c4] = ((const float4*)W1)[i];
    }
#pragma unroll 4
    for (int i = tid; i < 128 * 16; i += 128) {      // W2: 16 float4 per row
        int r = i >> 4, c4 = i & 15;
        ((float4*)(W2s + r * SW2))[c4] = ((const float4*)W2)[i];
    }
#pragma unroll 4
    for (int i = tid; i < 128 * 16; i += 128) {      // h: 16 float4 per row
        int r = i >> 4, c4 = i & 15;
        int node = nb + r;
        float4 v = make_float4(0.f, 0.f, 0.f, 0.f);
        if (node < N) v = ((const float4*)(g_h + (size_t)node * FDIM))[c4];
        ((float4*)(hs + r * SH))[c4] = v;
    }
    __syncthreads();

    // =================== Stage 1: hid = relu(h @ W1 + b1) ===================
    float acc1[2][16][4];
#pragma unroll
    for (int nt = 0; nt < 16; nt++) {
        float2 bv = *(const float2*)(b1 + nt * 8 + 2 * t);
#pragma unroll
        for (int mt = 0; mt < 2; mt++) {
            acc1[mt][nt][0] = bv.x; acc1[mt][nt][1] = bv.y;
            acc1[mt][nt][2] = bv.x; acc1[mt][nt][3] = bv.y;
        }
    }

#pragma unroll 1
    for (int kt = 0; kt < 8; kt++) {
        unsigned ah[2][4], al[2][4];
#pragma unroll
        for (int mt = 0; mt < 2; mt++) {
            int r0 = (wm + mt * 16 + g) * SH;
            int r1 = (wm + mt * 16 + g + 8) * SH;
            int c0 = kt * 8 + t;
            float f0 = hs[r0 + c0], f1 = hs[r1 + c0];
            float f2 = hs[r0 + c0 + 4], f3 = hs[r1 + c0 + 4];
            ah[mt][0] = f2tf32(f0); al[mt][0] = f2tf32(f0 - __uint_as_float(ah[mt][0]));
            ah[mt][1] = f2tf32(f1); al[mt][1] = f2tf32(f1 - __uint_as_float(ah[mt][1]));
            ah[mt][2] = f2tf32(f2); al[mt][2] = f2tf32(f2 - __uint_as_float(ah[mt][2]));
            ah[mt][3] = f2tf32(f3); al[mt][3] = f2tf32(f3 - __uint_as_float(ah[mt][3]));
        }
#pragma unroll
        for (int nt = 0; nt < 16; nt++) {
            float bf0 = W1s[(kt * 8 + t) * SW1 + nt * 8 + g];
            float bf1 = W1s[(kt * 8 + t + 4) * SW1 + nt * 8 + g];
            unsigned bh[2], bl[2];
            bh[0] = f2tf32(bf0); bl[0] = f2tf32(bf0 - __uint_as_float(bh[0]));
            bh[1] = f2tf32(bf1); bl[1] = f2tf32(bf1 - __uint_as_float(bh[1]));
#pragma unroll
            for (int mt = 0; mt < 2; mt++) {
                mma8(acc1[mt][nt], ah[mt], bh);
                mma8(acc1[mt][nt], ah[mt], bl);
                mma8(acc1[mt][nt], al[mt], bh);
            }
        }
    }

    // store hidden (ReLU) to smem — rows are private to this warp
#pragma unroll
    for (int mt = 0; mt < 2; mt++) {
        int r0 = (wm + mt * 16 + g) * SHD;
        int r1 = (wm + mt * 16 + g + 8) * SHD;
#pragma unroll
        for (int nt = 0; nt < 16; nt++) {
            int c = nt * 8 + 2 * t;
            float2 v0 = make_float2(fmaxf(acc1[mt][nt][0], 0.f), fmaxf(acc1[mt][nt][1], 0.f));
            float2 v1 = make_float2(fmaxf(acc1[mt][nt][2], 0.f), fmaxf(acc1[mt][nt][3], 0.f));
            *(float2*)(hid + r0 + c) = v0;
            *(float2*)(hid + r1 + c) = v1;
        }
    }
    __syncwarp();

    // =================== Stage 2: out = hid @ W2 + b2 ===================
    float acc2[2][8][4];
#pragma unroll
    for (int nt = 0; nt < 8; nt++) {
        float2 bv = *(const float2*)(b2 + nt * 8 + 2 * t);
#pragma unroll
        for (int mt = 0; mt < 2; mt++) {
            acc2[mt][nt][0] = bv.x; acc2[mt][nt][1] = bv.y;
            acc2[mt][nt][2] = bv.x; acc2[mt][nt][3] = bv.y;
        }
    }

#pragma unroll 1
    for (int kt = 0; kt < 16; kt++) {
        unsigned ah[2][4], al[2][4];
#pragma unroll
        for (int mt = 0; mt < 2; mt++) {
            int r0 = (wm + mt * 16 + g) * SHD;
            int r1 = (wm + mt * 16 + g + 8) * SHD;
            int c0 = kt * 8 + t;
            float f0 = hid[r0 + c0], f1 = hid[r1 + c0];
            float f2 = hid[r0 + c0 + 4], f3 = hid[r1 + c0 + 4];
            ah[mt][0] = f2tf32(f0); al[mt][0] = f2tf32(f0 - __uint_as_float(ah[mt][0]));
            ah[mt][1] = f2tf32(f1); al[mt][1] = f2tf32(f1 - __uint_as_float(ah[mt][1]));
            ah[mt][2] = f2tf32(f2); al[mt][2] = f2tf32(f2 - __uint_as_float(ah[mt][2]));
            ah[mt][3] = f2tf32(f3); al[mt][3] = f2tf32(f3 - __uint_as_float(ah[mt][3]));
        }
#pragma unroll
        for (int nt = 0; nt < 8; nt++) {
            float bf0 = W2s[(kt * 8 + t) * SW2 + nt * 8 + g];
            float bf1 = W2s[(kt * 8 + t + 4) * SW2 + nt * 8 + g];
            unsigned bh[2], bl[2];
            bh[0] = f2tf32(bf0); bl[0] = f2tf32(bf0 - __uint_as_float(bh[0]));
            bh[1] = f2tf32(bf1); bl[1] = f2tf32(bf1 - __uint_as_float(bh[1]));
#pragma unroll
            for (int mt = 0; mt < 2; mt++) {
                mma8(acc2[mt][nt], ah[mt], bh);
                mma8(acc2[mt][nt], ah[mt], bl);
                mma8(acc2[mt][nt], al[mt], bh);
            }
        }
    }

    // ---- write output ----
#pragma unroll
    for (int mt = 0; mt < 2; mt++) {
        int node0 = nb + wm + mt * 16 + g;
        int node1 = node0 + 8;
#pragma unroll
        for (int nt = 0; nt < 8; nt++) {
            int c = nt * 8 + 2 * t;
            if (node0 < N)
                *(float2*)(out + (size_t)node0 * FDIM + c) =
                    make_float2(acc2[mt][nt][0], acc2[mt][nt][1]);
            if (node1 < N)
                *(float2*)(out + (size_t)node1 * FDIM + c) =
                    make_float2(acc2[mt][nt][2], acc2[mt][nt][3]);
        }
    }
}

// ---------------------------------------------------------------------------
extern "C" void kernel_launch(void* const* d_in, const int* in_sizes, int n_in,
                              void* d_out, int out_size) {
    const float* x   = (const float*)d_in[0];
    const int*   ei  = (const int*)d_in[1];      // int32 (jax x64 disabled)
    const float* W1  = (const float*)d_in[2];
    const float* b1  = (const float*)d_in[3];
    const float* W2  = (const float*)d_in[4];
    const float* b2  = (const float*)d_in[5];
    const float* eps = (const float*)d_in[6];
    float* out = (float*)d_out;

    int N = in_sizes[0] / FDIM;       // 50000
    int E = in_sizes[1] / 2;          // 800000

    int n4 = N * FDIM / 4;
    init_h_kernel<<<(n4 + 255) / 256, 256>>>(x, eps, n4);

    long long sthreads = (long long)E * 16;
    int sblocks = (int)((sthreads + 255) / 256);
    scatter_kernel<<<sblocks, 256>>>(x, ei, E);

    static int smem_set = 0;
    (void)smem_set;
    cudaFuncSetAttribute(fused_mlp_kernel,
                         cudaFuncAttributeMaxDynamicSharedMemorySize,
                         SM_TOTAL * (int)sizeof(float));
    fused_mlp_kernel<<<(N + 127) / 128, 128, SM_TOTAL * sizeof(float)>>>(
        W1, b1, W2, b2, out, N);
}

// round 6
// speedup vs baseline: 1.6065x; 1.0525x over previous
#include <cuda_runtime.h>
#include <cstdint>

#define N_NODES_MAX 50000
#define FDIM 64
#define HDIM 128

// Scratch (no allocations allowed in kernel_launch)
__device__ __align__(16) float g_h[(size_t)N_NODES_MAX * FDIM];   // agg (scatter target)

// ---------------------------------------------------------------------------
// Kernel 1: zero g_h (write-only; (1+eps)*x is folded into the MLP load)
// ---------------------------------------------------------------------------
__global__ void zero_h_kernel(int n4) {
    int i = blockIdx.x * blockDim.x + threadIdx.x;
    if (i < n4) ((float4*)g_h)[i] = make_float4(0.f, 0.f, 0.f, 0.f);
}

// ---------------------------------------------------------------------------
// Kernel 2: scatter-add. edge_index int32. red.global.add.v4.f32 into g_h[row].
// ---------------------------------------------------------------------------
__global__ void scatter_kernel(const float* __restrict__ x,
                               const int* __restrict__ ei, int E) {
    long long i = (long long)blockIdx.x * blockDim.x + threadIdx.x;
    if (i >= (long long)E * 16) return;
    int e = (int)(i >> 4);
    int c = (int)(i & 15);
    int row = ei[e];
    int col = ei[E + e];
    float4 v = *(const float4*)(x + (size_t)col * FDIM + c * 4);
    float* dst = g_h + (size_t)row * FDIM + c * 4;
    asm volatile("red.global.add.v4.f32 [%0], {%1,%2,%3,%4};"
                 :: "l"(dst), "f"(v.x), "f"(v.y), "f"(v.z), "f"(v.w)
                 : "memory");
}

// ---------------------------------------------------------------------------
// Fused MLP: out = relu(h@W1+b1)@W2 + b2, h = (1+eps)*x + agg (computed on load)
// 3xTF32 compensation (hi*hi + hi*lo + lo*hi), fp32 accumulate.
//
// 128 nodes/block, 256 threads = 8 warps, each warp owns ONE m16 tile (16 rows).
// W1/W2 hi+lo are converted ONCE per block and stored in smem PRE-PACKED in
// b-fragment order: for (kt,nt,lane) a uint4 {bh0,bh1,bl0,bl1} -> one LDS.128.
// hid aliases h (barrier between stages).
//
// smem (u32 units):
//   W1p: 8*16*32 uint4  = 16384 u32 (64 KB)
//   W2p: 16*8*32 uint4  = 16384 u32 (64 KB)
//   act: union( h 128*68 f32 = 8704, hid 128*132 f32 = 16896 ) = 16896 (66 KB)
// total = 50176 u32 = 200704 B (~196 KB) -> 1 block/SM, 8 warps
// ---------------------------------------------------------------------------
#define SH   68
#define SHD  132
#define SM_W1P 0
#define SM_W2P 16384
#define SM_ACT 32768
#define SM_TOTAL_U32 (SM_ACT + 128 * SHD)   // 49664 u32 = 198656 B

__device__ __forceinline__ unsigned f2tf32(float x) {
    unsigned u;
    asm("cvt.rna.tf32.f32 %0, %1;" : "=r"(u) : "f"(x));
    return u;
}

__device__ __forceinline__ void mma8(float* d, const unsigned* a, const unsigned* b) {
    asm volatile(
        "mma.sync.aligned.m16n8k8.row.col.f32.tf32.tf32.f32 "
        "{%0,%1,%2,%3}, {%4,%5,%6,%7}, {%8,%9}, {%0,%1,%2,%3};\n"
        : "+f"(d[0]), "+f"(d[1]), "+f"(d[2]), "+f"(d[3])
        : "r"(a[0]), "r"(a[1]), "r"(a[2]), "r"(a[3]), "r"(b[0]), "r"(b[1]));
}

__device__ __forceinline__ uint4 pack_hilo(float f0, float f1) {
    uint4 u;
    u.x = f2tf32(f0);
    u.y = f2tf32(f1);
    u.z = f2tf32(f0 - __uint_as_float(u.x));
    u.w = f2tf32(f1 - __uint_as_float(u.y));
    return u;
}

__global__ __launch_bounds__(256, 1)
void fused_mlp_kernel(const float* __restrict__ x,
                      const float* __restrict__ W1, const float* __restrict__ b1,
                      const float* __restrict__ W2, const float* __restrict__ b2,
                      const float* __restrict__ eps,
                      float* __restrict__ out, int N) {
    extern __shared__ unsigned smu[];
    uint4* W1p = (uint4*)(smu + SM_W1P);
    uint4* W2p = (uint4*)(smu + SM_W2P);
    float* hsm = (float*)(smu + SM_ACT);     // stride SH,  128 rows
    float* hid = (float*)(smu + SM_ACT);     // stride SHD, 128 rows (aliases hsm)

    const int tid  = threadIdx.x;
    const int lane = tid & 31;
    const int wid  = tid >> 5;
    const int g = lane >> 2;
    const int t = lane & 3;
    const int nb = blockIdx.x * 128;
    const int wm = wid * 16;                 // warp's 16-row tile base

    // ---- prep: pack W1 hi/lo in b-frag order ----
#pragma unroll 4
    for (int idx = tid; idx < 8 * 16 * 32; idx += 256) {
        int li = idx & 31;
        int nt = (idx >> 5) & 15;
        int kt = idx >> 9;
        int k0 = kt * 8 + (li & 3);
        int n  = nt * 8 + (li >> 2);
        W1p[idx] = pack_hilo(W1[k0 * HDIM + n], W1[(k0 + 4) * HDIM + n]);
    }
    // ---- prep: pack W2 hi/lo ----
#pragma unroll 4
    for (int idx = tid; idx < 16 * 8 * 32; idx += 256) {
        int li = idx & 31;
        int nt = (idx >> 5) & 7;
        int kt = idx >> 8;
        int k0 = kt * 8 + (li & 3);
        int n  = nt * 8 + (li >> 2);
        W2p[idx] = pack_hilo(W2[k0 * FDIM + n], W2[(k0 + 4) * FDIM + n]);
    }
    // ---- load h tile: h = (1+eps)*x + agg ----
    {
        float s = 1.0f + __ldg(eps);
#pragma unroll 4
        for (int i = tid; i < 128 * 16; i += 256) {
            int r = i >> 4, c4 = i & 15;
            int node = nb + r;
            float4 v = make_float4(0.f, 0.f, 0.f, 0.f);
            if (node < N) {
                float4 a  = ((const float4*)(g_h + (size_t)node * FDIM))[c4];
                float4 xv = ((const float4*)(x   + (size_t)node * FDIM))[c4];
                v.x = fmaf(s, xv.x, a.x); v.y = fmaf(s, xv.y, a.y);
                v.z = fmaf(s, xv.z, a.z); v.w = fmaf(s, xv.w, a.w);
            }
            ((float4*)(hsm + r * SH))[c4] = v;
        }
    }
    __syncthreads();

    // =================== Stage 1: hid = relu(h @ W1 + b1) ===================
    float acc1[16][4];
#pragma unroll
    for (int nt = 0; nt < 16; nt++) {
        float2 bv = *(const float2*)(b1 + nt * 8 + 2 * t);
        acc1[nt][0] = bv.x; acc1[nt][1] = bv.y;
        acc1[nt][2] = bv.x; acc1[nt][3] = bv.y;
    }

#pragma unroll 1
    for (int kt = 0; kt < 8; kt++) {
        int r0 = (wm + g) * SH;
        int r1 = (wm + g + 8) * SH;
        int c0 = kt * 8 + t;
        float f0 = hsm[r0 + c0],     f1 = hsm[r1 + c0];
        float f2 = hsm[r0 + c0 + 4], f3 = hsm[r1 + c0 + 4];
        unsigned ah[4], al[4];
        ah[0] = f2tf32(f0); al[0] = f2tf32(f0 - __uint_as_float(ah[0]));
        ah[1] = f2tf32(f1); al[1] = f2tf32(f1 - __uint_as_float(ah[1]));
        ah[2] = f2tf32(f2); al[2] = f2tf32(f2 - __uint_as_float(ah[2]));
        ah[3] = f2tf32(f3); al[3] = f2tf32(f3 - __uint_as_float(ah[3]));
        const uint4* wrow = W1p + (kt * 16) * 32 + lane;
#pragma unroll
        for (int nt = 0; nt < 16; nt++) {
            uint4 w = wrow[nt * 32];
            unsigned bh[2] = {w.x, w.y}, bl[2] = {w.z, w.w};
            mma8(acc1[nt], ah, bh);
            mma8(acc1[nt], ah, bl);
            mma8(acc1[nt], al, bh);
        }
    }

    __syncthreads();   // everyone done reading hsm; safe to overwrite with hid

    {
        int r0 = (wm + g) * SHD;
        int r1 = (wm + g + 8) * SHD;
#pragma unroll
        for (int nt = 0; nt < 16; nt++) {
            int c = nt * 8 + 2 * t;
            *(float2*)(hid + r0 + c) =
                make_float2(fmaxf(acc1[nt][0], 0.f), fmaxf(acc1[nt][1], 0.f));
            *(float2*)(hid + r1 + c) =
                make_float2(fmaxf(acc1[nt][2], 0.f), fmaxf(acc1[nt][3], 0.f));
        }
    }
    __syncwarp();      // hid rows are warp-private; warp-level sync suffices

    // =================== Stage 2: out = hid @ W2 + b2 ===================
    float acc2[8][4];
#pragma unroll
    for (int nt = 0; nt < 8; nt++) {
        float2 bv = *(const float2*)(b2 + nt * 8 + 2 * t);
        acc2[nt][0] = bv.x; acc2[nt][1] = bv.y;
        acc2[nt][2] = bv.x; acc2[nt][3] = bv.y;
    }

#pragma unroll 1
    for (int kt = 0; kt < 16; kt++) {
        int r0 = (wm + g) * SHD;
        int r1 = (wm + g + 8) * SHD;
        int c0 = kt * 8 + t;
        float f0 = hid[r0 + c0],     f1 = hid[r1 + c0];
        float f2 = hid[r0 + c0 + 4], f3 = hid[r1 + c0 + 4];
        unsigned ah[4], al[4];
        ah[0] = f2tf32(f0); al[0] = f2tf32(f0 - __uint_as_float(ah[0]));
        ah[1] = f2tf32(f1); al[1] = f2tf32(f1 - __uint_as_float(ah[1]));
        ah[2] = f2tf32(f2); al[2] = f2tf32(f2 - __uint_as_float(ah[2]));
        ah[3] = f2tf32(f3); al[3] = f2tf32(f3 - __uint_as_float(ah[3]));
        const uint4* wrow = W2p + (kt * 8) * 32 + lane;
#pragma unroll
        for (int nt = 0; nt < 8; nt++) {
            uint4 w = wrow[nt * 32];
            unsigned bh[2] = {w.x, w.y}, bl[2] = {w.z, w.w};
            mma8(acc2[nt], ah, bh);
            mma8(acc2[nt], ah, bl);
            mma8(acc2[nt], al, bh);
        }
    }

    // ---- write output ----
    {
        int node0 = nb + wm + g;
        int node1 = node0 + 8;
#pragma unroll
        for (int nt = 0; nt < 8; nt++) {
            int c = nt * 8 + 2 * t;
            if (node0 < N)
                *(float2*)(out + (size_t)node0 * FDIM + c) =
                    make_float2(acc2[nt][0], acc2[nt][1]);
            if (node1 < N)
                *(float2*)(out + (size_t)node1 * FDIM + c) =
                    make_float2(acc2[nt][2], acc2[nt][3]);
        }
    }
}

// ---------------------------------------------------------------------------
extern "C" void kernel_launch(void* const* d_in, const int* in_sizes, int n_in,
                              void* d_out, int out_size) {
    const float* x   = (const float*)d_in[0];
    const int*   ei  = (const int*)d_in[1];      // int32 (jax x64 disabled)
    const float* W1  = (const float*)d_in[2];
    const float* b1  = (const float*)d_in[3];
    const float* W2  = (const float*)d_in[4];
    const float* b2  = (const float*)d_in[5];
    const float* eps = (const float*)d_in[6];
    float* out = (float*)d_out;

    int N = in_sizes[0] / FDIM;       // 50000
    int E = in_sizes[1] / 2;          // 800000

    int n4 = N * FDIM / 4;
    zero_h_kernel<<<(n4 + 255) / 256, 256>>>(n4);

    long long sthreads = (long long)E * 16;
    int sblocks = (int)((sthreads + 255) / 256);
    scatter_kernel<<<sblocks, 256>>>(x, ei, E);

    cudaFuncSetAttribute(fused_mlp_kernel,
                         cudaFuncAttributeMaxDynamicSharedMemorySize,
                         SM_TOTAL_U32 * (int)sizeof(unsigned));
    fused_mlp_kernel<<<(N + 127) / 128, 256, SM_TOTAL_U32 * sizeof(unsigned)>>>(
        x, W1, b1, W2, b2, eps, out, N);
}